// round 16
// baseline (speedup 1.0000x reference)
#include <cuda_runtime.h>

#define NT 256
#define XS   36    // X/H row stride (floats) — 144B rotates banks
#define PJS  68    // Pj row stride
#define HIDS 68    // emb hidden row stride
#define ATTS 52

// shared layout (float offsets)
#define OFF_X    0        // 51*36 = 1836
#define OFF_H    1840
#define OFF_PI   3680     // emb hidden 50*68+64=3464 / Pi 51*64=3264
#define OFF_PJ   7216     // 51*68 = 3468
#define OFF_ATT  10688    // 51*52 = 2652
#define OFF_W    13344    // weights: emb 5248 | G1 4232 | G2 4232
#define OFF_WE   OFF_W
#define OFF_WG1  (OFF_W + 5248)
#define OFF_WG2  (OFF_W + 5248 + 4232)
#define OFF_ST   (OFF_W + 5248 + 4232 + 4232)   // 27056, state 750
#define SMEM_FLOATS 27808
#define ROBOT_HID 3468

__device__ float g_O[1024 * 32];   // combined node-0 features per batch element

__device__ __forceinline__ void fma4(float4& acc, float s, const float4 w) {
    acc.x = fmaf(s, w.x, acc.x);
    acc.y = fmaf(s, w.y, acc.y);
    acc.z = fmaf(s, w.z, acc.z);
    acc.w = fmaf(s, w.w, acc.w);
}
__device__ __forceinline__ float comp(const float4 v, int s) {
    return s == 0 ? v.x : s == 1 ? v.y : s == 2 ? v.z : v.w;
}
__device__ __forceinline__ void relu4(float4& a) {
    a.x = fmaxf(a.x, 0.f); a.y = fmaxf(a.y, 0.f);
    a.z = fmaxf(a.z, 0.f); a.w = fmaxf(a.w, 0.f);
}

__device__ __forceinline__ void pair_acc(
    float& aA, float& aB, const float4 p, const float4 pa, const float4 pb,
    const float4 w1)
{
    aA = fmaf(fmaxf(p.x + pa.x, 0.f), w1.x, aA);
    aA = fmaf(fmaxf(p.y + pa.y, 0.f), w1.y, aA);
    aA = fmaf(fmaxf(p.z + pa.z, 0.f), w1.z, aA);
    aA = fmaf(fmaxf(p.w + pa.w, 0.f), w1.w, aA);
    aB = fmaf(fmaxf(p.x + pb.x, 0.f), w1.x, aB);
    aB = fmaf(fmaxf(p.y + pb.y, 0.f), w1.y, aB);
    aB = fmaf(fmaxf(p.z + pb.z, 0.f), w1.z, aB);
    aB = fmaf(fmaxf(p.w + pb.w, 0.f), w1.w, aB);
}

// softmax without max-subtract (shift-invariant; logits are tiny here)
__device__ __forceinline__ void softmax_row(
    float accA, float accB, float b1v, int i, int lane, int jb, bool vb,
    float* __restrict__ sAtt)
{
    float Aa = accA + b1v;
    float Ab = accB + b1v;
    float ea = Aa > 0.f ? Aa : 0.04f * Aa;   // leaky relu
    float eb = Ab > 0.f ? Ab : 0.04f * Ab;
    bool va = (i == 0) || (lane != 0);       // adj: rows >=1 exclude j==0
    float pa = va ? __expf(ea) : 0.f;
    float pb = vb ? __expf(eb) : 0.f;
    float s = pa + pb;
    #pragma unroll
    for (int off = 16; off > 0; off >>= 1)
        s += __shfl_xor_sync(0xffffffffu, s, off);
    float inv = 1.0f / s;
    sAtt[i * ATTS + lane] = pa * inv;
    if (vb) sAtt[i * ATTS + jb] = pb * inv;
}

// GAT layer 1: full 51-row layer. Weights pre-staged in sWg.
__device__ __forceinline__ void gat_full(
    float* sm, const float* __restrict__ sWg,
    const float* __restrict__ Xin, float* __restrict__ Hout,
    int tid, int wid, int lane)
{
    float* sPi  = sm + OFF_PI;
    float* sPj  = sm + OFF_PJ;
    float* sAtt = sm + OFF_ATT;

    // ---- P phase: 4 nodes x 4 cols outer-product tile per 16-thread group
    {
        int tq = tid & 15, nq = tid >> 4;
        if (nq < 13) {
            int n0 = nq * 4;
            const float4* x0 = (const float4*)(Xin + (n0 + 0) * XS);
            const float4* x1 = (const float4*)(Xin + (n0 + 1) * XS);
            const float4* x2 = (const float4*)(Xin + (n0 + 2) * XS);
            const float4* x3 = (const float4*)(Xin + (n0 + 3) * XS);
            float4 z = make_float4(0.f, 0.f, 0.f, 0.f);
            float4 aJ0 = z, aJ1 = z, aJ2 = z, aJ3 = z;
            float4 bI = ((const float4*)(sWg + 4096))[tq];
            float4 aI0 = bI, aI1 = bI, aI2 = bI, aI3 = bI;
            #pragma unroll 4
            for (int f4 = 0; f4 < 8; f4++) {
                float4 xv0 = x0[f4], xv1 = x1[f4], xv2 = x2[f4], xv3 = x3[f4];
                #pragma unroll
                for (int s = 0; s < 4; s++) {
                    int f = f4 * 4 + s;
                    float4 wI = ((const float4*)(sWg + f * 64))[tq];
                    float4 wJ = ((const float4*)(sWg + (f + 32) * 64))[tq];
                    float e0 = comp(xv0, s), e1 = comp(xv1, s);
                    float e2 = comp(xv2, s), e3 = comp(xv3, s);
                    fma4(aI0, e0, wI); fma4(aI1, e1, wI);
                    fma4(aI2, e2, wI); fma4(aI3, e3, wI);
                    fma4(aJ0, e0, wJ); fma4(aJ1, e1, wJ);
                    fma4(aJ2, e2, wJ); fma4(aJ3, e3, wJ);
                }
            }
            ((float4*)(sPi + (n0 + 0) * 64))[tq] = aI0;
            ((float4*)(sPi + (n0 + 1) * 64))[tq] = aI1;
            ((float4*)(sPi + (n0 + 2) * 64))[tq] = aI2;
            if (n0 + 3 < 51) ((float4*)(sPi + (n0 + 3) * 64))[tq] = aI3;
            ((float4*)(sPj + (n0 + 0) * PJS))[tq] = aJ0;
            ((float4*)(sPj + (n0 + 1) * PJS))[tq] = aJ1;
            ((float4*)(sPj + (n0 + 2) * PJS))[tq] = aJ2;
            if (n0 + 3 < 51) ((float4*)(sPj + (n0 + 3) * PJS))[tq] = aJ3;
        }
    }
    __syncthreads();

    // ---- pair phase, 4 rows per iteration (pa/pb/w1 amortized over 4 rows)
    {
        int jb  = lane + 32;
        int jbc = jb < 51 ? jb : 50;        // clamp keeps LDS conflict-free
        bool vb = jb < 51;
        const float4* w1v = (const float4*)(sWg + 4160);
        const float4* pav = (const float4*)(sPj + lane * PJS);
        const float4* pbv = (const float4*)(sPj + jbc * PJS);
        float b1v = sWg[4224];
        for (int i0 = wid; i0 < 51; i0 += 32) {
            int r1 = i0 + 8, r2 = i0 + 16, r3 = i0 + 24;
            bool h1 = r1 < 51, h2 = r2 < 51, h3 = r3 < 51;
            const float4* p0v = (const float4*)(sPi + i0 * 64);
            const float4* p1v = (const float4*)(sPi + (h1 ? r1 : i0) * 64);
            const float4* p2v = (const float4*)(sPi + (h2 ? r2 : i0) * 64);
            const float4* p3v = (const float4*)(sPi + (h3 ? r3 : i0) * 64);
            float aA0 = 0.f, aB0 = 0.f, aA1 = 0.f, aB1 = 0.f;
            float aA2 = 0.f, aB2 = 0.f, aA3 = 0.f, aB3 = 0.f;
            #pragma unroll 4
            for (int c4 = 0; c4 < 16; c4++) {
                float4 pa = pav[c4];
                float4 pb = pbv[c4];
                float4 w1 = w1v[c4];
                pair_acc(aA0, aB0, p0v[c4], pa, pb, w1);
                pair_acc(aA1, aB1, p1v[c4], pa, pb, w1);
                pair_acc(aA2, aB2, p2v[c4], pa, pb, w1);
                pair_acc(aA3, aB3, p3v[c4], pa, pb, w1);
            }
            softmax_row(aA0, aB0, b1v, i0, lane, jb, vb, sAtt);
            if (h1) softmax_row(aA1, aB1, b1v, r1, lane, jb, vb, sAtt);
            if (h2) softmax_row(aA2, aB2, b1v, r2, lane, jb, vb, sAtt);
            if (h3) softmax_row(aA3, aB3, b1v, r3, lane, jb, vb, sAtt);
        }
    }
    __syncthreads();

    // ---- H = att @ Xin, 4 rows per iteration (X loads amortized over 4 rows)
    for (int i0 = wid; i0 < 51; i0 += 32) {
        int r1 = i0 + 8, r2 = i0 + 16, r3 = i0 + 24;
        bool h1 = r1 < 51, h2 = r2 < 51, h3 = r3 < 51;
        const float* a0 = sAtt + i0 * ATTS;
        const float* a1 = sAtt + (h1 ? r1 : i0) * ATTS;
        const float* a2 = sAtt + (h2 ? r2 : i0) * ATTS;
        const float* a3 = sAtt + (h3 ? r3 : i0) * ATTS;
        const float4* a04 = (const float4*)a0;
        const float4* a14 = (const float4*)a1;
        const float4* a24 = (const float4*)a2;
        const float4* a34 = (const float4*)a3;
        float acc0 = 0.f, acc1 = 0.f, acc2 = 0.f, acc3 = 0.f;
        #pragma unroll 4
        for (int j4 = 0; j4 < 12; j4++) {
            float4 v0 = a04[j4];
            float4 v1 = a14[j4];
            float4 v2 = a24[j4];
            float4 v3 = a34[j4];
            float xa = Xin[(j4 * 4 + 0) * XS + lane];
            float xb = Xin[(j4 * 4 + 1) * XS + lane];
            float xc = Xin[(j4 * 4 + 2) * XS + lane];
            float xd = Xin[(j4 * 4 + 3) * XS + lane];
            acc0 = fmaf(v0.x, xa, acc0); acc1 = fmaf(v1.x, xa, acc1);
            acc2 = fmaf(v2.x, xa, acc2); acc3 = fmaf(v3.x, xa, acc3);
            acc0 = fmaf(v0.y, xb, acc0); acc1 = fmaf(v1.y, xb, acc1);
            acc2 = fmaf(v2.y, xb, acc2); acc3 = fmaf(v3.y, xb, acc3);
            acc0 = fmaf(v0.z, xc, acc0); acc1 = fmaf(v1.z, xc, acc1);
            acc2 = fmaf(v2.z, xc, acc2); acc3 = fmaf(v3.z, xc, acc3);
            acc0 = fmaf(v0.w, xd, acc0); acc1 = fmaf(v1.w, xd, acc1);
            acc2 = fmaf(v2.w, xd, acc2); acc3 = fmaf(v3.w, xd, acc3);
        }
        #pragma unroll
        for (int j = 48; j < 51; j++) {
            float xv = Xin[j * XS + lane];
            acc0 = fmaf(a0[j], xv, acc0);
            acc1 = fmaf(a1[j], xv, acc1);
            acc2 = fmaf(a2[j], xv, acc2);
            acc3 = fmaf(a3[j], xv, acc3);
        }
        Hout[i0 * XS + lane] = acc0;
        if (h1) Hout[r1 * XS + lane] = acc1;
        if (h2) Hout[r2 * XS + lane] = acc2;
        if (h3) Hout[r3 * XS + lane] = acc3;
    }
    __syncthreads();
}

__global__ void __launch_bounds__(NT, 2) value_net_kernel(
    const float* __restrict__ state,
    const float* __restrict__ wr_w0, const float* __restrict__ wr_b0,
    const float* __restrict__ wr_w1, const float* __restrict__ wr_b1,
    const float* __restrict__ wh_w0, const float* __restrict__ wh_b0,
    const float* __restrict__ wh_w1, const float* __restrict__ wh_b1,
    const float* __restrict__ g0_w0, const float* __restrict__ g0_b0,
    const float* __restrict__ g0_w1, const float* __restrict__ g0_b1,
    const float* __restrict__ g1_w0, const float* __restrict__ g1_b0,
    const float* __restrict__ g1_w1, const float* __restrict__ g1_b1)
{
    extern __shared__ float sm[];
    float* sX   = sm + OFF_X;
    float* sH   = sm + OFF_H;
    float* sPi  = sm + OFF_PI;
    float* sPj  = sm + OFF_PJ;
    float* sAtt = sm + OFF_ATT;
    float* sWE  = sm + OFF_WE;
    float* sW2  = sm + OFF_WE + 1088;
    float* sWG1 = sm + OFF_WG1;
    float* sWG2 = sm + OFF_WG2;
    float* sSt  = sm + OFF_ST;

    const int tid = threadIdx.x;
    const int wid = tid >> 5;
    const int lane = tid & 31;
    const int b = blockIdx.x;

    // ---- stage EVERYTHING once: state + all weights
    {
        const float* stb = state + b * 750;
        for (int i = tid; i < 750; i += NT) sSt[i] = stb[i];
        for (int i = tid; i < 384; i += NT) sWE[i] = wh_w0[i];
        for (int i = tid; i < 576; i += NT) sWE[448 + i] = wr_w0[i];
        if (tid < 64)       sWE[384 + tid]  = wh_b0[tid];
        else if (tid < 128) sWE[1024 + (tid - 64)] = wr_b0[tid - 64];
        for (int i = tid; i < 512; i += NT) ((float4*)sW2)[i] = ((const float4*)wh_w1)[i];
        for (int i = tid; i < 512; i += NT)
            ((float4*)(sW2 + 2080))[i] = ((const float4*)wr_w1)[i];
        if (tid < 32)      sW2[2048 + tid] = wh_b1[tid];
        else if (tid < 64) sW2[4128 + (tid - 32)] = wr_b1[tid - 32];
        for (int i = tid; i < 1024; i += NT) ((float4*)sWG1)[i] = ((const float4*)g0_w0)[i];
        if (tid < 64)       sWG1[4096 + tid] = g0_b0[tid];
        else if (tid < 128) sWG1[4160 + (tid - 64)] = g0_w1[tid - 64];
        else if (tid == 128) sWG1[4224] = g0_b1[0];
        for (int i = tid; i < 1024; i += NT) ((float4*)sWG2)[i] = ((const float4*)g1_w0)[i];
        if (tid < 64)       sWG2[4096 + tid] = g1_b0[tid];
        else if (tid < 128) sWG2[4160 + (tid - 64)] = g1_w1[tid - 64];
        else if (tid == 128) sWG2[4224] = g1_b1[0];
    }
    __syncthreads();

    // ---- embedding MLP layer 1: hidden (stride HIDS) in sPi
    for (int idx = tid; idx < 3200; idx += NT) {
        int n = idx >> 6, c = idx & 63;
        const float* hr = sSt + n * 15 + 9;
        float acc = sWE[384 + c];
        #pragma unroll
        for (int f = 0; f < 6; f++) acc = fmaf(hr[f], sWE[f * 64 + c], acc);
        sPi[n * HIDS + c] = fmaxf(acc, 0.f);
    }
    if (tid < 64) {   // robot hidden
        float acc = sWE[1024 + tid];
        #pragma unroll
        for (int f = 0; f < 9; f++) acc = fmaf(sSt[f], sWE[448 + f * 64 + tid], acc);
        sPi[ROBOT_HID + tid] = fmaxf(acc, 0.f);
    }
    __syncthreads();

    // ---- embedding MLP layer 2 -> X (51 x 32): 4 rows x 4 cols tiles
    {
        int tq = tid & 7, nq = tid >> 3;
        if (nq < 13) {
            int n0 = nq * 4;
            const float4* h0 = (const float4*)(sPi + (n0 + 0) * HIDS);
            const float4* h1 = (const float4*)(sPi + (n0 + 1) * HIDS);
            const float4* h2 = (const float4*)(sPi + (n0 + 2) * HIDS);
            const float4* h3 = (const float4*)(sPi + (n0 + 3) * HIDS);
            float4 bv = ((const float4*)(sW2 + 2048))[tq];
            float4 a0 = bv, a1 = bv, a2 = bv, a3 = bv;
            #pragma unroll 4
            for (int c4 = 0; c4 < 16; c4++) {
                float4 v0 = h0[c4], v1 = h1[c4], v2 = h2[c4], v3 = h3[c4];
                #pragma unroll
                for (int s = 0; s < 4; s++) {
                    float4 wv = ((const float4*)(sW2 + (c4 * 4 + s) * 32))[tq];
                    fma4(a0, comp(v0, s), wv);
                    fma4(a1, comp(v1, s), wv);
                    fma4(a2, comp(v2, s), wv);
                    fma4(a3, comp(v3, s), wv);
                }
            }
            relu4(a0); relu4(a1); relu4(a2); relu4(a3);
            ((float4*)(sX + (n0 + 1) * XS))[tq] = a0;
            if (n0 + 1 < 50) ((float4*)(sX + (n0 + 2) * XS))[tq] = a1;
            if (n0 + 2 < 50) ((float4*)(sX + (n0 + 3) * XS))[tq] = a2;
            if (n0 + 3 < 50) ((float4*)(sX + (n0 + 4) * XS))[tq] = a3;
        }
    }
    if (tid < 8) {   // robot embedding -> X[0]
        int q = tid;
        const float4* hid4 = (const float4*)(sPi + ROBOT_HID);
        float4 acc = ((const float4*)(sW2 + 4128))[q];
        #pragma unroll 4
        for (int c4 = 0; c4 < 16; c4++) {
            float4 h = hid4[c4];
            #pragma unroll
            for (int s = 0; s < 4; s++)
                fma4(acc, comp(h, s), ((const float4*)(sW2 + 2080 + (c4 * 4 + s) * 32))[q]);
        }
        relu4(acc);
        ((float4*)sX)[q] = acc;
    }
    __syncthreads();

    // ---- GAT layer 1 (full)
    gat_full(sm, sWG1, sX, sH, tid, wid, lane);

    // ---- GAT layer 2 P: Pj for all j (from sH), Pi row 0
    {
        int tq = tid & 15, nq = tid >> 4;
        if (nq < 13) {
            int n0 = nq * 4;
            const float4* x0 = (const float4*)(sH + (n0 + 0) * XS);
            const float4* x1 = (const float4*)(sH + (n0 + 1) * XS);
            const float4* x2 = (const float4*)(sH + (n0 + 2) * XS);
            const float4* x3 = (const float4*)(sH + (n0 + 3) * XS);
            float4 z = make_float4(0.f, 0.f, 0.f, 0.f);
            float4 aJ0 = z, aJ1 = z, aJ2 = z, aJ3 = z;
            #pragma unroll 4
            for (int f4 = 0; f4 < 8; f4++) {
                float4 xv0 = x0[f4], xv1 = x1[f4], xv2 = x2[f4], xv3 = x3[f4];
                #pragma unroll
                for (int s = 0; s < 4; s++) {
                    float4 wJ = ((const float4*)(sWG2 + (f4 * 4 + s + 32) * 64))[tq];
                    fma4(aJ0, comp(xv0, s), wJ);
                    fma4(aJ1, comp(xv1, s), wJ);
                    fma4(aJ2, comp(xv2, s), wJ);
                    fma4(aJ3, comp(xv3, s), wJ);
                }
            }
            ((float4*)(sPj + (n0 + 0) * PJS))[tq] = aJ0;
            ((float4*)(sPj + (n0 + 1) * PJS))[tq] = aJ1;
            ((float4*)(sPj + (n0 + 2) * PJS))[tq] = aJ2;
            if (n0 + 3 < 51) ((float4*)(sPj + (n0 + 3) * PJS))[tq] = aJ3;
        }
        if (tid >= 208 && tid < 224) {    // Pi row 0 (idle 16-group)
            int tq2 = tid - 208;
            const float4* x4p = (const float4*)sH;
            float4 aI = ((const float4*)(sWG2 + 4096))[tq2];
            #pragma unroll
            for (int f4 = 0; f4 < 8; f4++) {
                float4 xv = x4p[f4];
                #pragma unroll
                for (int s = 0; s < 4; s++)
                    fma4(aI, comp(xv, s), ((const float4*)(sWG2 + (f4 * 4 + s) * 64))[tq2]);
            }
            ((float4*)sPi)[tq2] = aI;
        }
    }
    __syncthreads();

    // ---- GAT2 tail: warp 0 does pair+softmax+H+combine, writes g_O; kernel ends
    if (wid == 0) {
        int jb  = lane + 32;
        int jbc = jb < 51 ? jb : 50;
        bool vb = jb < 51;
        const float4* p0v = (const float4*)sPi;
        const float4* w1v = (const float4*)(sWG2 + 4160);
        const float4* pav = (const float4*)(sPj + lane * PJS);
        const float4* pbv = (const float4*)(sPj + jbc * PJS);
        float aA = 0.f, aB = 0.f;
        #pragma unroll 8
        for (int c4 = 0; c4 < 16; c4++)
            pair_acc(aA, aB, p0v[c4], pav[c4], pbv[c4], w1v[c4]);
        softmax_row(aA, aB, sWG2[4224], 0, lane, jb, vb, sAtt);
        __syncwarp();
        const float* a0 = sAtt;
        const float4* a04 = (const float4*)a0;
        float acc = 0.f;
        #pragma unroll
        for (int j4 = 0; j4 < 12; j4++) {
            float4 v0 = a04[j4];
            acc = fmaf(v0.x, sH[(j4 * 4 + 0) * XS + lane], acc);
            acc = fmaf(v0.y, sH[(j4 * 4 + 1) * XS + lane], acc);
            acc = fmaf(v0.z, sH[(j4 * 4 + 2) * XS + lane], acc);
            acc = fmaf(v0.w, sH[(j4 * 4 + 3) * XS + lane], acc);
        }
        #pragma unroll
        for (int j = 48; j < 51; j++)
            acc = fmaf(a0[j], sH[j * XS + lane], acc);
        g_O[b * 32 + lane] = acc + sH[lane] + sX[lane];   // H1[0]+H2[0]+X[0]
    }
}

// ---- kernel 2: value MLP (R14 split-f form) + PDL: prefetch weights into L2
//      BEFORE the grid dependency resolves, then sync and consume g_O.
__global__ void __launch_bounds__(256) value_mlp_kernel(
    const float* __restrict__ v_w0, const float* __restrict__ v_b0,
    const float* __restrict__ v_w1, const float* __restrict__ v_b1,
    const float* __restrict__ v_w2, const float* __restrict__ v_b2,
    float* __restrict__ out)
{
    __shared__ float sO[32];
    __shared__ float h1[152];
    __shared__ float part[200];
    __shared__ float h2[104];
    const int b = blockIdx.x;
    const int tid = threadIdx.x;
    const int lane = tid & 31;

    // ---- pre-sync: prefetch weight lines into L2 (independent of primary grid)
    if (b < 64) {   // 64 CTAs cover all weights; others skip
        // v_w0: 4800 floats = 150 lines of 128B; v_w1: 15000 floats = 469 lines
        for (int i = b * 256 + tid; i < 150 + 469; i += 64 * 256) {
            const float* p = (i < 150) ? (v_w0 + i * 32)
                                       : (v_w1 + (i - 150) * 32);
            asm volatile("prefetch.global.L2 [%0];" :: "l"(p));
        }
    }

    // ---- wait for primary grid (g_O producers) to complete
    cudaGridDependencySynchronize();

    if (tid < 32) sO[tid] = g_O[b * 32 + tid];
    __syncthreads();

    // layer 1: 32 -> 150 (fully unrolled independent loads)
    if (tid < 150) {
        float acc = __ldg(v_b0 + tid);
        #pragma unroll
        for (int f = 0; f < 32; f++)
            acc = fmaf(sO[f], __ldg(v_w0 + f * 150 + tid), acc);
        h1[tid] = fmaxf(acc, 0.f);
    }
    __syncthreads();

    // layer 2: 150 -> 100, f split in halves across thread pairs (tid, tid+100)
    if (tid < 200) {
        int half = (tid >= 100) ? 1 : 0;
        int c = tid - half * 100;
        int f0 = half * 75;
        const float* w = v_w1 + c;
        float a0 = 0.f, a1 = 0.f;
        #pragma unroll
        for (int k = 0; k < 74; k += 2) {
            a0 = fmaf(h1[f0 + k],     __ldg(w + (f0 + k) * 100),     a0);
            a1 = fmaf(h1[f0 + k + 1], __ldg(w + (f0 + k + 1) * 100), a1);
        }
        a0 = fmaf(h1[f0 + 74], __ldg(w + (f0 + 74) * 100), a0);
        part[tid] = a0 + a1;
    }
    __syncthreads();

    if (tid < 100)
        h2[tid] = fmaxf(part[tid] + part[tid + 100] + __ldg(v_b1 + tid), 0.f);
    __syncthreads();

    // layer 3: 100 -> 1
    if (tid < 32) {
        float acc = 0.f;
        #pragma unroll
        for (int f = lane; f < 100; f += 32)
            acc = fmaf(h2[f], __ldg(v_w2 + f), acc);
        #pragma unroll
        for (int off = 16; off > 0; off >>= 1)
            acc += __shfl_xor_sync(0xffffffffu, acc, off);
        if (lane == 0) out[b] = fmaxf(acc + __ldg(v_b2), 0.f);
    }
}

extern "C" void kernel_launch(void* const* d_in, const int* in_sizes, int n_in,
                              void* d_out, int out_size)
{
    const float* state = (const float*)d_in[0];
    // d_in[1] = dropout (unused)
    const float* wr_w0 = (const float*)d_in[2];
    const float* wr_b0 = (const float*)d_in[3];
    const float* wr_w1 = (const float*)d_in[4];
    const float* wr_b1 = (const float*)d_in[5];
    const float* wh_w0 = (const float*)d_in[6];
    const float* wh_b0 = (const float*)d_in[7];
    const float* wh_w1 = (const float*)d_in[8];
    const float* wh_b1 = (const float*)d_in[9];
    const float* g0_w0 = (const float*)d_in[10];
    const float* g0_b0 = (const float*)d_in[11];
    const float* g0_w1 = (const float*)d_in[12];
    const float* g0_b1 = (const float*)d_in[13];
    const float* g1_w0 = (const float*)d_in[14];
    const float* g1_b0 = (const float*)d_in[15];
    const float* g1_w1 = (const float*)d_in[16];
    const float* g1_b1 = (const float*)d_in[17];
    const float* v_w0  = (const float*)d_in[18];
    const float* v_b0  = (const float*)d_in[19];
    const float* v_w1  = (const float*)d_in[20];
    const float* v_b1  = (const float*)d_in[21];
    const float* v_w2  = (const float*)d_in[22];
    const float* v_b2  = (const float*)d_in[23];
    float* out = (float*)d_out;

    int B = in_sizes[0] / 750;
    size_t smem = SMEM_FLOATS * sizeof(float);
    cudaFuncSetAttribute(value_net_kernel,
                         cudaFuncAttributeMaxDynamicSharedMemorySize, (int)smem);
    value_net_kernel<<<B, NT, smem>>>(
        state,
        wr_w0, wr_b0, wr_w1, wr_b1,
        wh_w0, wh_b0, wh_w1, wh_b1,
        g0_w0, g0_b0, g0_w1, g0_b1,
        g1_w0, g1_b0, g1_w1, g1_b1);

    // secondary launch with programmatic stream serialization (PDL)
    cudaLaunchConfig_t cfg = {};
    cfg.gridDim = dim3(B, 1, 1);
    cfg.blockDim = dim3(256, 1, 1);
    cfg.dynamicSmemBytes = 0;
    cfg.stream = 0;
    cudaLaunchAttribute attrs[1];
    attrs[0].id = cudaLaunchAttributeProgrammaticStreamSerialization;
    attrs[0].val.programmaticStreamSerializationAllowed = 1;
    cfg.attrs = attrs;
    cfg.numAttrs = 1;
    cudaLaunchKernelEx(&cfg, value_mlp_kernel,
                       v_w0, v_b0, v_w1, v_b1, v_w2, v_b2, out);
}

// round 17
// speedup vs baseline: 1.1029x; 1.1029x over previous
#include <cuda_runtime.h>

#define NT 256
#define XS   36    // X/H row stride (floats) — 144B rotates banks
#define PJS  68    // Pj row stride
#define HIDS 68    // emb hidden row stride
#define ATTS 52

// shared layout (float offsets)
#define OFF_X    0        // 51*36 = 1836
#define OFF_H    1840
#define OFF_PI   3680     // emb hidden 50*68+64=3464 / Pi 51*64=3264 / mlp scratch
#define OFF_PJ   7216     // 51*68 = 3468
#define OFF_ATT  10688    // 51*52 = 2652
#define OFF_W    13344    // weights: emb 5248 | G1 4232 | G2 4232
#define OFF_WE   OFF_W
#define OFF_WG1  (OFF_W + 5248)
#define OFF_WG2  (OFF_W + 5248 + 4232)
#define OFF_ST   (OFF_W + 5248 + 4232 + 4232)   // 27056, state 750
#define SMEM_FLOATS 27808
#define ROBOT_HID 3468

// mlp scratch inside PI region (dead after GAT2 tail)
#define MLP_H1   0      // 152
#define MLP_PART 160    // 200
#define MLP_H2   368    // 104
#define MLP_O    480    // 32

__device__ __forceinline__ void fma4(float4& acc, float s, const float4 w) {
    acc.x = fmaf(s, w.x, acc.x);
    acc.y = fmaf(s, w.y, acc.y);
    acc.z = fmaf(s, w.z, acc.z);
    acc.w = fmaf(s, w.w, acc.w);
}
__device__ __forceinline__ float comp(const float4 v, int s) {
    return s == 0 ? v.x : s == 1 ? v.y : s == 2 ? v.z : v.w;
}
__device__ __forceinline__ void relu4(float4& a) {
    a.x = fmaxf(a.x, 0.f); a.y = fmaxf(a.y, 0.f);
    a.z = fmaxf(a.z, 0.f); a.w = fmaxf(a.w, 0.f);
}

__device__ __forceinline__ void pair_acc(
    float& aA, float& aB, const float4 p, const float4 pa, const float4 pb,
    const float4 w1)
{
    aA = fmaf(fmaxf(p.x + pa.x, 0.f), w1.x, aA);
    aA = fmaf(fmaxf(p.y + pa.y, 0.f), w1.y, aA);
    aA = fmaf(fmaxf(p.z + pa.z, 0.f), w1.z, aA);
    aA = fmaf(fmaxf(p.w + pa.w, 0.f), w1.w, aA);
    aB = fmaf(fmaxf(p.x + pb.x, 0.f), w1.x, aB);
    aB = fmaf(fmaxf(p.y + pb.y, 0.f), w1.y, aB);
    aB = fmaf(fmaxf(p.z + pb.z, 0.f), w1.z, aB);
    aB = fmaf(fmaxf(p.w + pb.w, 0.f), w1.w, aB);
}

// softmax without max-subtract (shift-invariant; logits are tiny here)
__device__ __forceinline__ void softmax_row(
    float accA, float accB, float b1v, int i, int lane, int jb, bool vb,
    float* __restrict__ sAtt)
{
    float Aa = accA + b1v;
    float Ab = accB + b1v;
    float ea = Aa > 0.f ? Aa : 0.04f * Aa;   // leaky relu
    float eb = Ab > 0.f ? Ab : 0.04f * Ab;
    bool va = (i == 0) || (lane != 0);       // adj: rows >=1 exclude j==0
    float pa = va ? __expf(ea) : 0.f;
    float pb = vb ? __expf(eb) : 0.f;
    float s = pa + pb;
    #pragma unroll
    for (int off = 16; off > 0; off >>= 1)
        s += __shfl_xor_sync(0xffffffffu, s, off);
    float inv = 1.0f / s;
    sAtt[i * ATTS + lane] = pa * inv;
    if (vb) sAtt[i * ATTS + jb] = pb * inv;
}

// GAT layer 1: full 51-row layer. Weights pre-staged in sWg.
__device__ __forceinline__ void gat_full(
    float* sm, const float* __restrict__ sWg,
    const float* __restrict__ Xin, float* __restrict__ Hout,
    int tid, int wid, int lane)
{
    float* sPi  = sm + OFF_PI;
    float* sPj  = sm + OFF_PJ;
    float* sAtt = sm + OFF_ATT;

    // ---- P phase: 4 nodes x 4 cols outer-product tile per 16-thread group
    {
        int tq = tid & 15, nq = tid >> 4;
        if (nq < 13) {
            int n0 = nq * 4;
            const float4* x0 = (const float4*)(Xin + (n0 + 0) * XS);
            const float4* x1 = (const float4*)(Xin + (n0 + 1) * XS);
            const float4* x2 = (const float4*)(Xin + (n0 + 2) * XS);
            const float4* x3 = (const float4*)(Xin + (n0 + 3) * XS);
            float4 z = make_float4(0.f, 0.f, 0.f, 0.f);
            float4 aJ0 = z, aJ1 = z, aJ2 = z, aJ3 = z;
            float4 bI = ((const float4*)(sWg + 4096))[tq];
            float4 aI0 = bI, aI1 = bI, aI2 = bI, aI3 = bI;
            #pragma unroll 4
            for (int f4 = 0; f4 < 8; f4++) {
                float4 xv0 = x0[f4], xv1 = x1[f4], xv2 = x2[f4], xv3 = x3[f4];
                #pragma unroll
                for (int s = 0; s < 4; s++) {
                    int f = f4 * 4 + s;
                    float4 wI = ((const float4*)(sWg + f * 64))[tq];
                    float4 wJ = ((const float4*)(sWg + (f + 32) * 64))[tq];
                    float e0 = comp(xv0, s), e1 = comp(xv1, s);
                    float e2 = comp(xv2, s), e3 = comp(xv3, s);
                    fma4(aI0, e0, wI); fma4(aI1, e1, wI);
                    fma4(aI2, e2, wI); fma4(aI3, e3, wI);
                    fma4(aJ0, e0, wJ); fma4(aJ1, e1, wJ);
                    fma4(aJ2, e2, wJ); fma4(aJ3, e3, wJ);
                }
            }
            ((float4*)(sPi + (n0 + 0) * 64))[tq] = aI0;
            ((float4*)(sPi + (n0 + 1) * 64))[tq] = aI1;
            ((float4*)(sPi + (n0 + 2) * 64))[tq] = aI2;
            if (n0 + 3 < 51) ((float4*)(sPi + (n0 + 3) * 64))[tq] = aI3;
            ((float4*)(sPj + (n0 + 0) * PJS))[tq] = aJ0;
            ((float4*)(sPj + (n0 + 1) * PJS))[tq] = aJ1;
            ((float4*)(sPj + (n0 + 2) * PJS))[tq] = aJ2;
            if (n0 + 3 < 51) ((float4*)(sPj + (n0 + 3) * PJS))[tq] = aJ3;
        }
    }
    __syncthreads();

    // ---- pair phase, 4 rows per iteration (pa/pb/w1 amortized over 4 rows)
    {
        int jb  = lane + 32;
        int jbc = jb < 51 ? jb : 50;        // clamp keeps LDS conflict-free
        bool vb = jb < 51;
        const float4* w1v = (const float4*)(sWg + 4160);
        const float4* pav = (const float4*)(sPj + lane * PJS);
        const float4* pbv = (const float4*)(sPj + jbc * PJS);
        float b1v = sWg[4224];
        for (int i0 = wid; i0 < 51; i0 += 32) {
            int r1 = i0 + 8, r2 = i0 + 16, r3 = i0 + 24;
            bool h1 = r1 < 51, h2 = r2 < 51, h3 = r3 < 51;
            const float4* p0v = (const float4*)(sPi + i0 * 64);
            const float4* p1v = (const float4*)(sPi + (h1 ? r1 : i0) * 64);
            const float4* p2v = (const float4*)(sPi + (h2 ? r2 : i0) * 64);
            const float4* p3v = (const float4*)(sPi + (h3 ? r3 : i0) * 64);
            float aA0 = 0.f, aB0 = 0.f, aA1 = 0.f, aB1 = 0.f;
            float aA2 = 0.f, aB2 = 0.f, aA3 = 0.f, aB3 = 0.f;
            #pragma unroll 4
            for (int c4 = 0; c4 < 16; c4++) {
                float4 pa = pav[c4];
                float4 pb = pbv[c4];
                float4 w1 = w1v[c4];
                pair_acc(aA0, aB0, p0v[c4], pa, pb, w1);
                pair_acc(aA1, aB1, p1v[c4], pa, pb, w1);
                pair_acc(aA2, aB2, p2v[c4], pa, pb, w1);
                pair_acc(aA3, aB3, p3v[c4], pa, pb, w1);
            }
            softmax_row(aA0, aB0, b1v, i0, lane, jb, vb, sAtt);
            if (h1) softmax_row(aA1, aB1, b1v, r1, lane, jb, vb, sAtt);
            if (h2) softmax_row(aA2, aB2, b1v, r2, lane, jb, vb, sAtt);
            if (h3) softmax_row(aA3, aB3, b1v, r3, lane, jb, vb, sAtt);
        }
    }
    __syncthreads();

    // ---- H = att @ Xin, 4 rows per iteration (X loads amortized over 4 rows)
    for (int i0 = wid; i0 < 51; i0 += 32) {
        int r1 = i0 + 8, r2 = i0 + 16, r3 = i0 + 24;
        bool h1 = r1 < 51, h2 = r2 < 51, h3 = r3 < 51;
        const float* a0 = sAtt + i0 * ATTS;
        const float* a1 = sAtt + (h1 ? r1 : i0) * ATTS;
        const float* a2 = sAtt + (h2 ? r2 : i0) * ATTS;
        const float* a3 = sAtt + (h3 ? r3 : i0) * ATTS;
        const float4* a04 = (const float4*)a0;
        const float4* a14 = (const float4*)a1;
        const float4* a24 = (const float4*)a2;
        const float4* a34 = (const float4*)a3;
        float acc0 = 0.f, acc1 = 0.f, acc2 = 0.f, acc3 = 0.f;
        #pragma unroll 4
        for (int j4 = 0; j4 < 12; j4++) {
            float4 v0 = a04[j4];
            float4 v1 = a14[j4];
            float4 v2 = a24[j4];
            float4 v3 = a34[j4];
            float xa = Xin[(j4 * 4 + 0) * XS + lane];
            float xb = Xin[(j4 * 4 + 1) * XS + lane];
            float xc = Xin[(j4 * 4 + 2) * XS + lane];
            float xd = Xin[(j4 * 4 + 3) * XS + lane];
            acc0 = fmaf(v0.x, xa, acc0); acc1 = fmaf(v1.x, xa, acc1);
            acc2 = fmaf(v2.x, xa, acc2); acc3 = fmaf(v3.x, xa, acc3);
            acc0 = fmaf(v0.y, xb, acc0); acc1 = fmaf(v1.y, xb, acc1);
            acc2 = fmaf(v2.y, xb, acc2); acc3 = fmaf(v3.y, xb, acc3);
            acc0 = fmaf(v0.z, xc, acc0); acc1 = fmaf(v1.z, xc, acc1);
            acc2 = fmaf(v2.z, xc, acc2); acc3 = fmaf(v3.z, xc, acc3);
            acc0 = fmaf(v0.w, xd, acc0); acc1 = fmaf(v1.w, xd, acc1);
            acc2 = fmaf(v2.w, xd, acc2); acc3 = fmaf(v3.w, xd, acc3);
        }
        #pragma unroll
        for (int j = 48; j < 51; j++) {
            float xv = Xin[j * XS + lane];
            acc0 = fmaf(a0[j], xv, acc0);
            acc1 = fmaf(a1[j], xv, acc1);
            acc2 = fmaf(a2[j], xv, acc2);
            acc3 = fmaf(a3[j], xv, acc3);
        }
        Hout[i0 * XS + lane] = acc0;
        if (h1) Hout[r1 * XS + lane] = acc1;
        if (h2) Hout[r2 * XS + lane] = acc2;
        if (h3) Hout[r3 * XS + lane] = acc3;
    }
    __syncthreads();
}

__global__ void __launch_bounds__(NT, 2) value_net_kernel(
    const float* __restrict__ state,
    const float* __restrict__ wr_w0, const float* __restrict__ wr_b0,
    const float* __restrict__ wr_w1, const float* __restrict__ wr_b1,
    const float* __restrict__ wh_w0, const float* __restrict__ wh_b0,
    const float* __restrict__ wh_w1, const float* __restrict__ wh_b1,
    const float* __restrict__ g0_w0, const float* __restrict__ g0_b0,
    const float* __restrict__ g0_w1, const float* __restrict__ g0_b1,
    const float* __restrict__ g1_w0, const float* __restrict__ g1_b0,
    const float* __restrict__ g1_w1, const float* __restrict__ g1_b1,
    const float* __restrict__ v_w0, const float* __restrict__ v_b0,
    const float* __restrict__ v_w1, const float* __restrict__ v_b1,
    const float* __restrict__ v_w2, const float* __restrict__ v_b2,
    float* __restrict__ out, int B)
{
    extern __shared__ float sm[];
    float* sX   = sm + OFF_X;
    float* sH   = sm + OFF_H;
    float* sPi  = sm + OFF_PI;
    float* sPj  = sm + OFF_PJ;
    float* sAtt = sm + OFF_ATT;
    float* sWE  = sm + OFF_WE;
    float* sW2  = sm + OFF_WE + 1088;
    float* sWG1 = sm + OFF_WG1;
    float* sWG2 = sm + OFF_WG2;
    float* sSt  = sm + OFF_ST;

    const int tid = threadIdx.x;
    const int wid = tid >> 5;
    const int lane = tid & 31;

    // ---- stage ALL weights ONCE per CTA (persistent grid)
    {
        for (int i = tid; i < 384; i += NT) sWE[i] = wh_w0[i];
        for (int i = tid; i < 576; i += NT) sWE[448 + i] = wr_w0[i];
        if (tid < 64)       sWE[384 + tid]  = wh_b0[tid];
        else if (tid < 128) sWE[1024 + (tid - 64)] = wr_b0[tid - 64];
        for (int i = tid; i < 512; i += NT) ((float4*)sW2)[i] = ((const float4*)wh_w1)[i];
        for (int i = tid; i < 512; i += NT)
            ((float4*)(sW2 + 2080))[i] = ((const float4*)wr_w1)[i];
        if (tid < 32)      sW2[2048 + tid] = wh_b1[tid];
        else if (tid < 64) sW2[4128 + (tid - 32)] = wr_b1[tid - 32];
        for (int i = tid; i < 1024; i += NT) ((float4*)sWG1)[i] = ((const float4*)g0_w0)[i];
        if (tid < 64)       sWG1[4096 + tid] = g0_b0[tid];
        else if (tid < 128) sWG1[4160 + (tid - 64)] = g0_w1[tid - 64];
        else if (tid == 128) sWG1[4224] = g0_b1[0];
        for (int i = tid; i < 1024; i += NT) ((float4*)sWG2)[i] = ((const float4*)g1_w0)[i];
        if (tid < 64)       sWG2[4096 + tid] = g1_b0[tid];
        else if (tid < 128) sWG2[4160 + (tid - 64)] = g1_w1[tid - 64];
        else if (tid == 128) sWG2[4224] = g1_b1[0];
    }
    __syncthreads();

    for (int b = blockIdx.x; b < B; b += gridDim.x) {
        // ---- stage state row for this element
        {
            const float* stb = state + b * 750;
            for (int i = tid; i < 750; i += NT) sSt[i] = stb[i];
        }
        __syncthreads();

        // ---- embedding MLP layer 1: hidden (stride HIDS) in sPi
        for (int idx = tid; idx < 3200; idx += NT) {
            int n = idx >> 6, c = idx & 63;
            const float* hr = sSt + n * 15 + 9;
            float acc = sWE[384 + c];
            #pragma unroll
            for (int f = 0; f < 6; f++) acc = fmaf(hr[f], sWE[f * 64 + c], acc);
            sPi[n * HIDS + c] = fmaxf(acc, 0.f);
        }
        if (tid < 64) {   // robot hidden
            float acc = sWE[1024 + tid];
            #pragma unroll
            for (int f = 0; f < 9; f++) acc = fmaf(sSt[f], sWE[448 + f * 64 + tid], acc);
            sPi[ROBOT_HID + tid] = fmaxf(acc, 0.f);
        }
        __syncthreads();

        // ---- embedding MLP layer 2 -> X (51 x 32): 4 rows x 4 cols tiles
        {
            int tq = tid & 7, nq = tid >> 3;
            if (nq < 13) {
                int n0 = nq * 4;
                const float4* h0 = (const float4*)(sPi + (n0 + 0) * HIDS);
                const float4* h1 = (const float4*)(sPi + (n0 + 1) * HIDS);
                const float4* h2 = (const float4*)(sPi + (n0 + 2) * HIDS);
                const float4* h3 = (const float4*)(sPi + (n0 + 3) * HIDS);
                float4 bv = ((const float4*)(sW2 + 2048))[tq];
                float4 a0 = bv, a1 = bv, a2 = bv, a3 = bv;
                #pragma unroll 4
                for (int c4 = 0; c4 < 16; c4++) {
                    float4 v0 = h0[c4], v1 = h1[c4], v2 = h2[c4], v3 = h3[c4];
                    #pragma unroll
                    for (int s = 0; s < 4; s++) {
                        float4 wv = ((const float4*)(sW2 + (c4 * 4 + s) * 32))[tq];
                        fma4(a0, comp(v0, s), wv);
                        fma4(a1, comp(v1, s), wv);
                        fma4(a2, comp(v2, s), wv);
                        fma4(a3, comp(v3, s), wv);
                    }
                }
                relu4(a0); relu4(a1); relu4(a2); relu4(a3);
                ((float4*)(sX + (n0 + 1) * XS))[tq] = a0;
                if (n0 + 1 < 50) ((float4*)(sX + (n0 + 2) * XS))[tq] = a1;
                if (n0 + 2 < 50) ((float4*)(sX + (n0 + 3) * XS))[tq] = a2;
                if (n0 + 3 < 50) ((float4*)(sX + (n0 + 4) * XS))[tq] = a3;
            }
        }
        if (tid < 8) {   // robot embedding -> X[0]
            int q = tid;
            const float4* hid4 = (const float4*)(sPi + ROBOT_HID);
            float4 acc = ((const float4*)(sW2 + 4128))[q];
            #pragma unroll 4
            for (int c4 = 0; c4 < 16; c4++) {
                float4 h = hid4[c4];
                #pragma unroll
                for (int s = 0; s < 4; s++)
                    fma4(acc, comp(h, s), ((const float4*)(sW2 + 2080 + (c4 * 4 + s) * 32))[q]);
            }
            relu4(acc);
            ((float4*)sX)[q] = acc;
        }
        __syncthreads();

        // ---- GAT layer 1 (full)
        gat_full(sm, sWG1, sX, sH, tid, wid, lane);

        // ---- GAT layer 2 P: Pj for all j (from sH), Pi row 0
        {
            int tq = tid & 15, nq = tid >> 4;
            if (nq < 13) {
                int n0 = nq * 4;
                const float4* x0 = (const float4*)(sH + (n0 + 0) * XS);
                const float4* x1 = (const float4*)(sH + (n0 + 1) * XS);
                const float4* x2 = (const float4*)(sH + (n0 + 2) * XS);
                const float4* x3 = (const float4*)(sH + (n0 + 3) * XS);
                float4 z = make_float4(0.f, 0.f, 0.f, 0.f);
                float4 aJ0 = z, aJ1 = z, aJ2 = z, aJ3 = z;
                #pragma unroll 4
                for (int f4 = 0; f4 < 8; f4++) {
                    float4 xv0 = x0[f4], xv1 = x1[f4], xv2 = x2[f4], xv3 = x3[f4];
                    #pragma unroll
                    for (int s = 0; s < 4; s++) {
                        float4 wJ = ((const float4*)(sWG2 + (f4 * 4 + s + 32) * 64))[tq];
                        fma4(aJ0, comp(xv0, s), wJ);
                        fma4(aJ1, comp(xv1, s), wJ);
                        fma4(aJ2, comp(xv2, s), wJ);
                        fma4(aJ3, comp(xv3, s), wJ);
                    }
                }
                ((float4*)(sPj + (n0 + 0) * PJS))[tq] = aJ0;
                ((float4*)(sPj + (n0 + 1) * PJS))[tq] = aJ1;
                ((float4*)(sPj + (n0 + 2) * PJS))[tq] = aJ2;
                if (n0 + 3 < 51) ((float4*)(sPj + (n0 + 3) * PJS))[tq] = aJ3;
            }
            if (tid >= 208 && tid < 224) {    // Pi row 0 (idle 16-group)
                int tq2 = tid - 208;
                const float4* x4p = (const float4*)sH;
                float4 aI = ((const float4*)(sWG2 + 4096))[tq2];
                #pragma unroll
                for (int f4 = 0; f4 < 8; f4++) {
                    float4 xv = x4p[f4];
                    #pragma unroll
                    for (int s = 0; s < 4; s++)
                        fma4(aI, comp(xv, s), ((const float4*)(sWG2 + (f4 * 4 + s) * 64))[tq2]);
                }
                ((float4*)sPi)[tq2] = aI;
            }
        }
        __syncthreads();

        // ---- GAT2 tail: warp 0 pair+softmax+H+combine -> sO (smem, no global)
        if (wid == 0) {
            int jb  = lane + 32;
            int jbc = jb < 51 ? jb : 50;
            bool vb = jb < 51;
            const float4* p0v = (const float4*)sPi;
            const float4* w1v = (const float4*)(sWG2 + 4160);
            const float4* pav = (const float4*)(sPj + lane * PJS);
            const float4* pbv = (const float4*)(sPj + jbc * PJS);
            float aA = 0.f, aB = 0.f;
            #pragma unroll 8
            for (int c4 = 0; c4 < 16; c4++)
                pair_acc(aA, aB, p0v[c4], pav[c4], pbv[c4], w1v[c4]);
            softmax_row(aA, aB, sWG2[4224], 0, lane, jb, vb, sAtt);
            __syncwarp();
            const float* a0 = sAtt;
            const float4* a04 = (const float4*)a0;
            float acc = 0.f;
            #pragma unroll
            for (int j4 = 0; j4 < 12; j4++) {
                float4 v0 = a04[j4];
                acc = fmaf(v0.x, sH[(j4 * 4 + 0) * XS + lane], acc);
                acc = fmaf(v0.y, sH[(j4 * 4 + 1) * XS + lane], acc);
                acc = fmaf(v0.z, sH[(j4 * 4 + 2) * XS + lane], acc);
                acc = fmaf(v0.w, sH[(j4 * 4 + 3) * XS + lane], acc);
            }
            #pragma unroll
            for (int j = 48; j < 51; j++)
                acc = fmaf(a0[j], sH[j * XS + lane], acc);
            sPi[MLP_O + lane] = acc + sH[lane] + sX[lane];   // H1[0]+H2[0]+X[0]
        }
        __syncthreads();

        // ---- inline value MLP (split-f form), scratch in sPi region
        float* sO   = sPi + MLP_O;
        float* h1   = sPi + MLP_H1;
        float* part = sPi + MLP_PART;
        float* h2   = sPi + MLP_H2;

        // layer 1: 32 -> 150
        if (tid < 150) {
            float acc = __ldg(v_b0 + tid);
            #pragma unroll
            for (int f = 0; f < 32; f++)
                acc = fmaf(sO[f], __ldg(v_w0 + f * 150 + tid), acc);
            h1[tid] = fmaxf(acc, 0.f);
        }
        __syncthreads();

        // layer 2: 150 -> 100, f split in halves across thread pairs
        if (tid < 200) {
            int half = (tid >= 100) ? 1 : 0;
            int c = tid - half * 100;
            int f0 = half * 75;
            const float* w = v_w1 + c;
            float a0 = 0.f, a1 = 0.f;
            #pragma unroll
            for (int k = 0; k < 74; k += 2) {
                a0 = fmaf(h1[f0 + k],     __ldg(w + (f0 + k) * 100),     a0);
                a1 = fmaf(h1[f0 + k + 1], __ldg(w + (f0 + k + 1) * 100), a1);
            }
            a0 = fmaf(h1[f0 + 74], __ldg(w + (f0 + 74) * 100), a0);
            part[tid] = a0 + a1;
        }
        __syncthreads();

        if (tid < 100)
            h2[tid] = fmaxf(part[tid] + part[tid + 100] + __ldg(v_b1 + tid), 0.f);
        __syncthreads();

        // layer 3: 100 -> 1
        if (tid < 32) {
            float acc = 0.f;
            #pragma unroll
            for (int f = lane; f < 100; f += 32)
                acc = fmaf(h2[f], __ldg(v_w2 + f), acc);
            #pragma unroll
            for (int off = 16; off > 0; off >>= 1)
                acc += __shfl_xor_sync(0xffffffffu, acc, off);
            if (lane == 0) out[b] = fmaxf(acc + __ldg(v_b2), 0.f);
        }
        __syncthreads();   // protect sSt/sPi before next element
    }
}

extern "C" void kernel_launch(void* const* d_in, const int* in_sizes, int n_in,
                              void* d_out, int out_size)
{
    const float* state = (const float*)d_in[0];
    // d_in[1] = dropout (unused)
    const float* wr_w0 = (const float*)d_in[2];
    const float* wr_b0 = (const float*)d_in[3];
    const float* wr_w1 = (const float*)d_in[4];
    const float* wr_b1 = (const float*)d_in[5];
    const float* wh_w0 = (const float*)d_in[6];
    const float* wh_b0 = (const float*)d_in[7];
    const float* wh_w1 = (const float*)d_in[8];
    const float* wh_b1 = (const float*)d_in[9];
    const float* g0_w0 = (const float*)d_in[10];
    const float* g0_b0 = (const float*)d_in[11];
    const float* g0_w1 = (const float*)d_in[12];
    const float* g0_b1 = (const float*)d_in[13];
    const float* g1_w0 = (const float*)d_in[14];
    const float* g1_b0 = (const float*)d_in[15];
    const float* g1_w1 = (const float*)d_in[16];
    const float* g1_b1 = (const float*)d_in[17];
    const float* v_w0  = (const float*)d_in[18];
    const float* v_b0  = (const float*)d_in[19];
    const float* v_w1  = (const float*)d_in[20];
    const float* v_b1  = (const float*)d_in[21];
    const float* v_w2  = (const float*)d_in[22];
    const float* v_b2  = (const float*)d_in[23];
    float* out = (float*)d_out;

    int B = in_sizes[0] / 750;
    int grid = B < 296 ? B : 296;   // 2 CTAs/SM x 148 SMs
    size_t smem = SMEM_FLOATS * sizeof(float);
    cudaFuncSetAttribute(value_net_kernel,
                         cudaFuncAttributeMaxDynamicSharedMemorySize, (int)smem);
    value_net_kernel<<<grid, NT, smem>>>(
        state,
        wr_w0, wr_b0, wr_w1, wr_b1,
        wh_w0, wh_b0, wh_w1, wh_b1,
        g0_w0, g0_b0, g0_w1, g0_b1,
        g1_w0, g1_b0, g1_w1, g1_b1,
        v_w0, v_b0, v_w1, v_b1, v_w2, v_b2,
        out, B);
}